// round 13
// baseline (speedup 1.0000x reference)
#include <cuda_runtime.h>
#include <stdint.h>

// RVAEModel: out[b, c, g] = weight[idx[b, g], c]
//   idx:    [256, 64]  (int32 OR int64 — detected by tiny kernel)
//   weight: fp32 [1024, 1024]
//   out:    fp32 [256, 1024, 8, 8] (= [256, 1024, 64])
//
// Shared-memory-free: each thread owns a 4x4 (g x c) block.
//   4x LDG.128 (rows row[4gq..4gq+3], same c-quad) -> in-register transpose
//   -> 4x STG.128 along g.
// Warp layout: gq spans 4 consecutive values, cq spans 8 consecutive ->
//   loads:  4 full 128B lines per warp-op
//   stores: 8 aligned 64B half-lines per warp-op (full 32B sectors)
// No smem, no barriers, no cp.async: latency hidden purely by occupancy.

static constexpr int BS = 256;
static constexpr int M  = 64;    // tokens per sample (g)
static constexpr int C  = 1024;  // channels

__device__ int g_idx_is64; // 1 if indices buffer is int64, 0 if int32

// Indices are in [0, 1024). If buffer is LE int64, odd 32-bit words of the
// first 64 indices are all zero; for int32 data P = (1/1024)^64 ~ 0.
// Reads 128 words — in-bounds either way.
__global__ void detect_idx_dtype(const unsigned int* __restrict__ idx_words)
{
    unsigned int acc = 0;
    #pragma unroll
    for (int i = 0; i < 64; i++) acc |= idx_words[2 * i + 1];
    g_idx_is64 = (acc == 0) ? 1 : 0;
}

__global__ __launch_bounds__(256)
void rvae_direct(const void*  __restrict__ idx_raw,
                 const float* __restrict__ w,
                 float*       __restrict__ out)
{
    const int b     = blockIdx.y;
    const int cbase = blockIdx.x * 128; // block's 128-channel span
    const int t     = threadIdx.x;      // 256 threads = 8 warps
    const int wrp   = t >> 5;
    const int lane  = t & 31;

    // Warp covers 4 consecutive g-quads x 8 consecutive c-quads.
    const int gq = (wrp & 3) * 4 + ((lane >> 3) & 3); // 0..15
    const int cq = (wrp >> 2) * 8 + (lane & 7);       // 0..15 (x4 c within 64)

    // Rows for this thread's 4 g's (g = 4*gq + k).
    int row[4];
    if (g_idx_is64) {
        const long long* ip = reinterpret_cast<const long long*>(idx_raw) + b * M + 4 * gq;
        #pragma unroll
        for (int k = 0; k < 4; k++) row[k] = (int)ip[k];
    } else {
        const int* ip = reinterpret_cast<const int*>(idx_raw) + b * M + 4 * gq;
        #pragma unroll
        for (int k = 0; k < 4; k++) row[k] = ip[k];
    }

    const int c0 = cbase + 4 * cq; // first channel of this thread's block(s)

    // Issue all 8 independent loads first (MLP=8).
    float4 v[2][4];
    #pragma unroll
    for (int j = 0; j < 2; j++) {      // two 64-c halves of the 128-c span
        #pragma unroll
        for (int k = 0; k < 4; k++) {
            v[j][k] = *reinterpret_cast<const float4*>(
                w + (size_t)row[k] * C + c0 + j * 64);
        }
    }

    // Transpose + store: out[b, c0 + j*64 + j2, 4*gq + k].
    float* ob = out + (size_t)b * (C * M) + (size_t)c0 * M + 4 * gq;
    #pragma unroll
    for (int j = 0; j < 2; j++) {
        const float4 a = v[j][0], bb = v[j][1], cc = v[j][2], dd = v[j][3];
        float* oj = ob + (size_t)(j * 64) * M;
        *reinterpret_cast<float4*>(oj + 0 * M) = float4{a.x, bb.x, cc.x, dd.x};
        *reinterpret_cast<float4*>(oj + 1 * M) = float4{a.y, bb.y, cc.y, dd.y};
        *reinterpret_cast<float4*>(oj + 2 * M) = float4{a.z, bb.z, cc.z, dd.z};
        *reinterpret_cast<float4*>(oj + 3 * M) = float4{a.w, bb.w, cc.w, dd.w};
    }
}

extern "C" void kernel_launch(void* const* d_in, const int* in_sizes, int n_in,
                              void* d_out, int out_size)
{
    // indices: 16384 elements; weight: 1048576 elements (fp32)
    const void*  idx;
    const float* w;
    if (in_sizes[0] == BS * M) {
        idx = d_in[0];
        w   = (const float*)d_in[1];
    } else {
        idx = d_in[1];
        w   = (const float*)d_in[0];
    }

    detect_idx_dtype<<<1, 1>>>((const unsigned int*)idx);

    dim3 grid(C / 128, BS); // (8, 256) = 2048 blocks
    rvae_direct<<<grid, 256>>>(idx, w, (float*)d_out);
}

// round 15
// speedup vs baseline: 1.8114x; 1.8114x over previous
#include <cuda_runtime.h>
#include <stdint.h>

// RVAEModel: out[b, c, g] = weight[idx[b, g], c]
//   idx:    [256, 64]  (int32 OR int64 — detected in-warp, no extra kernel)
//   weight: fp32 [1024, 1024]
//   out:    fp32 [256, 1024, 8, 8] (= [256, 1024, 64])
//
// Block = (b, 256-wide c-span) = 8 subtiles of 32 c. 128 threads, ~9 CTAs/SM
// (25KB smem). 3-deep cp.async ring, ONE barrier per subtile, exact waits:
//   committed at iter-h wait = tiles 0..min(h+1,7); allow = {2,1,...,1,0}
//   iter h: wait_group -> syncthreads (publishes tile h, proves tile h-1
//   consumed) -> gather(h+2) into (h-1)%3 -> LDS.128 x4 -> reg 4x4
//   transpose -> STG.128 x4 (coalesced).
// Dtype detect: warp votes on odd 32-bit words of the FIRST 64 indices only
// (512B probe — in-bounds under both interpretations). P[wrong] ~ 1024^-32.

static constexpr int BS = 256;
static constexpr int M  = 64;    // tokens per sample (g)
static constexpr int C  = 1024;  // channels
static constexpr int NT = 8;     // subtiles per block
static constexpr int SC = 32;    // subtile c-width
static constexpr int NB = 3;     // tin ring depth

__global__ __launch_bounds__(128)
void rvae_gather_transpose(const void*  __restrict__ idx_raw,
                           const float* __restrict__ w,
                           float*       __restrict__ out)
{
    const int b   = blockIdx.y;
    const int cqb = blockIdx.x * (NT * SC); // block base channel (256-span)
    const int t   = threadIdx.x;            // 128 threads

    __shared__ __align__(128) float4 tin[NB][M * 8]; // 3 x 8KB, swizzled

    // Gather lanes: c4 = t&7 (float4 col), gb = t>>3 (0..15), g = gb + 16i.
    const int c4 = t & 7;
    const int gb = t >> 3;

    // ---- in-warp dtype detect (probe limited to first 64 indices: 512B,
    // in-bounds whether the buffer is 64KB int32 or 128KB int64). If data is
    // LE int64 (values < 1024), all odd words are 0; if int32, each sampled
    // odd word is a random index, nonzero w.p. 1023/1024; 32 samples/warp.
    const unsigned int probe =
        reinterpret_cast<const unsigned int*>(idx_raw)[2 * (t & 63) + 1];
    const bool is32 = __any_sync(0xffffffffu, probe != 0u);

    // ---- row loads with the detected (warp-uniform) dtype, in-bounds ----
    int row[4];
    if (is32) {
        #pragma unroll
        for (int i = 0; i < 4; i++)
            row[i] = reinterpret_cast<const int*>(idx_raw)[b * M + gb + 16 * i];
    } else {
        #pragma unroll
        for (int i = 0; i < 4; i++)
            row[i] = (int)reinterpret_cast<const long long*>(idx_raw)[b * M + gb + 16 * i];
    }

    auto gather = [&](int h) {
        const int c0  = cqb + SC * h;
        float4*   buf = tin[h % NB];
        #pragma unroll
        for (int i = 0; i < 4; i++) {
            const int g = gb + 16 * i;
            const float*   src = w + (size_t)row[i] * C + c0 + (c4 << 2);
            const uint32_t dst = (uint32_t)__cvta_generic_to_shared(
                &buf[g * 8 + (c4 ^ ((g >> 2) & 7))]);
            asm volatile("cp.async.cg.shared.global [%0], [%1], 16;"
                         :: "r"(dst), "l"(src) : "memory");
        }
        asm volatile("cp.async.commit_group;" ::: "memory");
    };

    gather(0);
    gather(1);
    gather(2);

    // Transpose unit: 4g x 4c. ub = g-quad (0..15), uc = c-quad (0..7).
    const int ub = t & 15;
    const int uc = t >> 4;
    const int sc = uc ^ (ub & 7); // swizzled tin column ((4ub+k)>>2 & 7 == ub&7)

    #pragma unroll
    for (int h = 0; h < NT; h++) {
        // Exact accounting: committed tiles = 0..min(h+1, NT-1); need 0..h.
        const int allow = (h == 0) ? 2 : (h < NT - 1) ? 1 : 0;
        if (allow == 2)      asm volatile("cp.async.wait_group 2;" ::: "memory");
        else if (allow == 1) asm volatile("cp.async.wait_group 1;" ::: "memory");
        else                 asm volatile("cp.async.wait_group 0;" ::: "memory");
        __syncthreads(); // publishes tile h; proves tile h-1 consumed by all

        // Buffer (h+2)%3 == (h-1)%3 is free now: refill for tile h+2.
        if (h >= 1 && h + 2 < NT) gather(h + 2);

        const float4* ti = tin[h % NB];
        const float4 r0 = ti[(4 * ub + 0) * 8 + sc];
        const float4 r1 = ti[(4 * ub + 1) * 8 + sc];
        const float4 r2 = ti[(4 * ub + 2) * 8 + sc];
        const float4 r3 = ti[(4 * ub + 3) * 8 + sc];

        // out[b, cqb + SC*h + 4*uc + j, 4*ub + k]: two contiguous 256B
        // segments per warp STG -> fully coalesced.
        float* ob = out + (size_t)b * (C * M)
                        + (size_t)(cqb + SC * h) * M + 4 * ub;
        *reinterpret_cast<float4*>(ob + (4 * uc + 0) * M) = float4{r0.x, r1.x, r2.x, r3.x};
        *reinterpret_cast<float4*>(ob + (4 * uc + 1) * M) = float4{r0.y, r1.y, r2.y, r3.y};
        *reinterpret_cast<float4*>(ob + (4 * uc + 2) * M) = float4{r0.z, r1.z, r2.z, r3.z};
        *reinterpret_cast<float4*>(ob + (4 * uc + 3) * M) = float4{r0.w, r1.w, r2.w, r3.w};
    }
}

extern "C" void kernel_launch(void* const* d_in, const int* in_sizes, int n_in,
                              void* d_out, int out_size)
{
    // indices: 16384 elements; weight: 1048576 elements (fp32)
    const void*  idx;
    const float* w;
    if (in_sizes[0] == BS * M) {
        idx = d_in[0];
        w   = (const float*)d_in[1];
    } else {
        idx = d_in[1];
        w   = (const float*)d_in[0];
    }

    dim3 grid(C / (NT * SC), BS); // (4, 256) = 1024 blocks
    rvae_gather_transpose<<<grid, 128>>>(idx, w, (float*)d_out);
}